// round 14
// baseline (speedup 1.0000x reference)
#include <cuda_runtime.h>
#include <cstdint>

#define T_STEPS 512
#define B_SZ 128
#define I_SZ 256
#define H_SZ 256
#define BH (B_SZ*H_SZ)

typedef unsigned long long ull;

// ---------------- f32x2 helpers ----------------
__device__ __forceinline__ ull pack2(float x, float y) {
    ull r; asm("mov.b64 %0, {%1,%2};" : "=l"(r) : "f"(x), "f"(y)); return r;
}
__device__ __forceinline__ void unpack2(float& x, float& y, ull v) {
    asm("mov.b64 {%0,%1}, %2;" : "=f"(x), "=f"(y) : "l"(v));
}
__device__ __forceinline__ void fma2(ull& d, ull a, ull b) {
    asm("fma.rn.f32x2 %0, %1, %2, %0;" : "+l"(d) : "l"(a), "l"(b));
}
__device__ __forceinline__ ull mul2(ull a, ull b) {
    ull r; asm("mul.rn.f32x2 %0, %1, %2;" : "=l"(r) : "l"(a), "l"(b)); return r;
}

// ---------------- device scratch ----------------
__device__ float d_zx[4*B_SZ*I_SZ];                       // (4,B,I)
__device__ float d_zh[4*B_SZ*H_SZ];                       // (4,B,H)
__device__ float d_xpre[(size_t)T_STEPS*B_SZ*4*H_SZ];     // (T,B,4,H)
__device__ unsigned g_bars[8*32];                         // one 128B line per b-group

__global__ void reset_kernel() { if (threadIdx.x < 256) g_bars[threadIdx.x] = 0u; }

// ---------------- masks ----------------
__device__ __forceinline__ float concrete_mask(float u) {
    const float EPSC = 1e-7f;
    float logit_p = logf(0.25f + EPSC) - logf(0.75f + EPSC);
    float lu = logf(u + EPSC) - logf(1.0f - u + EPSC);
    float x = (logit_p + lu) / 0.1f;
    float s = 1.0f / (1.0f + expf(-x));
    return (1.0f - s) / 0.75f;
}

__global__ void mask_kernel(const float* __restrict__ ux, const float* __restrict__ uh) {
    int i = blockIdx.x * blockDim.x + threadIdx.x;
    if (i < 4*B_SZ*I_SZ) {
        d_zx[i] = concrete_mask(ux[i]);
        d_zh[i] = concrete_mask(uh[i]);
    }
}

// ---------------- x_pre GEMM (BK=16, FFMA2) ----------------
#define XB_BM 128
#define XB_BN 64
#define XB_BK 16

__global__ __launch_bounds__(256) void xpre_kernel(
    const float* __restrict__ input, const float* __restrict__ W, const float* __restrict__ Wb)
{
    __shared__ float As[XB_BK][XB_BM+4];
    __shared__ float Bs[XB_BK][XB_BN+4];
    int g  = blockIdx.z;
    int t  = blockIdx.x;
    int n0 = blockIdx.y * XB_BN;
    int tid = threadIdx.x;
    int tx = tid & 15, ty = tid >> 4;

    ull acc[4][4];
    #pragma unroll
    for (int p = 0; p < 4; p++)
        #pragma unroll
        for (int c = 0; c < 4; c++) acc[p][c] = 0ull;

    const float* inpBase = input + (size_t)t * (B_SZ*I_SZ);
    const float* zxBase  = d_zx + g * (B_SZ*I_SZ);
    const float* wBase   = W + (size_t)g * (H_SZ*I_SZ) + (size_t)n0 * I_SZ;

    int lrow   = tid >> 2;
    int lchunk = (tid & 3) * 4;

    for (int kk0 = 0; kk0 < I_SZ; kk0 += XB_BK) {
        #pragma unroll
        for (int it = 0; it < 2; it++) {
            int row = lrow + it*64;
            float4 av = *(const float4*)(inpBase + row*I_SZ + kk0 + lchunk);
            float4 zv = *(const float4*)(zxBase  + row*I_SZ + kk0 + lchunk);
            As[lchunk+0][row] = av.x*zv.x;
            As[lchunk+1][row] = av.y*zv.y;
            As[lchunk+2][row] = av.z*zv.z;
            As[lchunk+3][row] = av.w*zv.w;
        }
        {
            float4 wv = *(const float4*)(wBase + lrow*I_SZ + kk0 + lchunk);
            Bs[lchunk+0][lrow] = wv.x;
            Bs[lchunk+1][lrow] = wv.y;
            Bs[lchunk+2][lrow] = wv.z;
            Bs[lchunk+3][lrow] = wv.w;
        }
        __syncthreads();
        #pragma unroll
        for (int kk = 0; kk < XB_BK; kk++) {
            float4 b4 = *(const float4*)&Bs[kk][tx*4];
            ulonglong2 a01 = *(const ulonglong2*)&As[kk][ty*8];
            ulonglong2 a23 = *(const ulonglong2*)&As[kk][ty*8+4];
            ull ap[4] = {a01.x, a01.y, a23.x, a23.y};
            ull bb[4] = {pack2(b4.x,b4.x), pack2(b4.y,b4.y),
                         pack2(b4.z,b4.z), pack2(b4.w,b4.w)};
            #pragma unroll
            for (int p = 0; p < 4; p++)
                #pragma unroll
                for (int c = 0; c < 4; c++)
                    fma2(acc[p][c], ap[p], bb[c]);
        }
        __syncthreads();
    }
    float4 wb = *(const float4*)(Wb + g*H_SZ + n0 + tx*4);
    #pragma unroll
    for (int p = 0; p < 4; p++) {
        float lo[4], hi[4];
        #pragma unroll
        for (int c = 0; c < 4; c++) unpack2(lo[c], hi[c], acc[p][c]);
        int b0r = ty*8 + 2*p;
        size_t o0 = (((size_t)t*B_SZ + b0r)*4 + g) * H_SZ + n0 + tx*4;
        size_t o1 = (((size_t)t*B_SZ + b0r+1)*4 + g) * H_SZ + n0 + tx*4;
        *(float4*)(d_xpre + o0) = make_float4(lo[0]+wb.x, lo[1]+wb.y, lo[2]+wb.z, lo[3]+wb.w);
        *(float4*)(d_xpre + o1) = make_float4(hi[0]+wb.x, hi[1]+wb.y, hi[2]+wb.z, hi[3]+wb.w);
    }
}

// ---------------- persistent recurrent kernel: 8x8 register tile ----------------
// 128 CTAs (8 b-groups x 16 k-CTAs), 256 threads.
// Thread tile: 8k x 8b x 16h. warp=(g,kt); lane=(bt,hr).
// smem: U_s[4g][4224] | hm_s[4g][4224] | s_s[16hr][4g][16k][20] | c_s[256]
#define RK_THREADS 256
#define GB 4224                      // per-g block: 256 rows *16 + 16 pads *8
#define SST 20                       // s_s row stride (80B, float4-aligned)
#define RK_SMEM_FLOATS (4*GB + 4*GB + 16*4*16*SST + 256)
#define RK_SMEM_BYTES (RK_SMEM_FLOATS*4)

__global__ __launch_bounds__(RK_THREADS, 1) void recurrent_kernel(
    const float* __restrict__ U, const float* __restrict__ Ub, float* __restrict__ out)
{
    extern __shared__ float sm[];
    float* U_s  = sm;                        // 4*4224 = 16896 floats
    float* hm_s = U_s + 4*GB;                // 16896 floats
    float* s_s  = hm_s + 4*GB;               // 20480 floats
    float* c_s  = s_s + 16*4*16*SST;         // 256

    int tid = threadIdx.x;
    int bi = blockIdx.x >> 4;  int b0 = bi * 16;
    int ki = blockIdx.x & 15;  int k0 = ki * 16;

    // ---- one-time loads ----
    // U_s[g][h-row][k]: row offset = g*GB + h*16 + (h>>4)*8
    for (int e = tid; e < 16384; e += RK_THREADS) {
        int g = e >> 12; int k = (e >> 8) & 15; int h = e & 255;
        U_s[g*GB + h*16 + (h >> 4)*8 + k] = U[((size_t)(g*H_SZ + k0 + k))*H_SZ + h];
    }
    for (int e = tid; e < 4*GB; e += RK_THREADS) hm_s[e] = 0.f;   // t=0 state
    c_s[tid] = 0.f;

    // zh registers: thread h=tid, zr[g][bp] packs batches (2bp, 2bp+1)
    ull zr[4][8];
    {
        int h = tid;
        #pragma unroll
        for (int g = 0; g < 4; g++)
            #pragma unroll
            for (int bp = 0; bp < 8; bp++) {
                float z0 = d_zh[((size_t)(g*B_SZ + b0 + 2*bp))*H_SZ + h];
                float z1 = d_zh[((size_t)(g*B_SZ + b0 + 2*bp+1))*H_SZ + h];
                zr[g][bp] = pack2(z0, z1);
            }
    }

    int eb = tid >> 4, ek = tid & 15;   // epilogue cell (b,k)
    float ubr[4];
    #pragma unroll
    for (int g = 0; g < 4; g++) ubr[g] = Ub[g*H_SZ + k0 + ek];
    __syncthreads();

    // ---- GEMM thread mapping ----
    int w = tid >> 5, lane = tid & 31;
    int g  = w & 3;
    int kt = w >> 2;             // 0..1  -> k base kt*8
    int bt = lane >> 4;          // 0..1  -> b base bt*8
    int hr = lane & 15;          // h range [hr*16, hr*16+16)
    const float* Uptr = U_s  + g*GB + hr*264 + kt*8;   // hr*16*16 + hr*8 = hr*264
    const float* Hptr = hm_s + g*GB + hr*264 + bt*8;
    float* Sbase = s_s + ((hr*4 + g)*16 + kt*8)*SST + bt*8;

    // staging row bases (thread h=tid)
    float* hrow[4];
    {
        int h = tid;
        #pragma unroll
        for (int gg = 0; gg < 4; gg++)
            hrow[gg] = hm_s + gg*GB + h*16 + (h >> 4)*8;
    }

    float* hn     = out;
    float* ht_out = out + (size_t)T_STEPS*BH;
    float* ct_out = ht_out + BH;

    unsigned* mybar = &g_bars[bi*32];

    // initial x_pre prefetch (t=0)
    const float* xpp = d_xpre + (((size_t)(b0 + eb))*4)*H_SZ + k0 + ek;
    float xp0 = __ldcs(xpp);
    float xp1 = __ldcs(xpp + H_SZ);
    float xp2 = __ldcs(xpp + 2*H_SZ);
    float xp3 = __ldcs(xpp + 3*H_SZ);

    for (int t = 0; t < T_STEPS; t++) {
        // ---- phase 1: stage hm = h_prev * zh (t=0 pre-zeroed) ----
        if (t > 0) {
            const float* hprev = hn + (size_t)(t-1)*BH + (size_t)b0*H_SZ;
            int h = tid;
            float hv0[8], hv1[8];
            #pragma unroll
            for (int bp = 0; bp < 8; bp++) {
                hv0[bp] = __ldcg(hprev + (2*bp)*H_SZ + h);
                hv1[bp] = __ldcg(hprev + (2*bp+1)*H_SZ + h);
            }
            #pragma unroll
            for (int gg = 0; gg < 4; gg++) {
                ull m[8];
                #pragma unroll
                for (int bp = 0; bp < 8; bp++)
                    m[bp] = mul2(pack2(hv0[bp], hv1[bp]), zr[gg][bp]);
                ulonglong2 v01; v01.x = m[0]; v01.y = m[1];
                ulonglong2 v23; v23.x = m[2]; v23.y = m[3];
                ulonglong2 v45; v45.x = m[4]; v45.y = m[5];
                ulonglong2 v67; v67.x = m[6]; v67.y = m[7];
                *(ulonglong2*)(hrow[gg])      = v01;
                *(ulonglong2*)(hrow[gg] + 4)  = v23;
                *(ulonglong2*)(hrow[gg] + 8)  = v45;
                *(ulonglong2*)(hrow[gg] + 12) = v67;
            }
        }
        __syncthreads();

        // ---- phase 2: GEMM 8k x 8b over 16 h per thread ----
        {
            ull acc[8][4];
            #pragma unroll
            for (int j = 0; j < 8; j++)
                #pragma unroll
                for (int p = 0; p < 4; p++) acc[j][p] = 0ull;

            #pragma unroll 4
            for (int i = 0; i < 16; i++) {
                float4 u0 = *(const float4*)(Uptr + i*16);
                float4 u1 = *(const float4*)(Uptr + i*16 + 4);
                ulonglong2 mA = *(const ulonglong2*)(Hptr + i*16);
                ulonglong2 mB = *(const ulonglong2*)(Hptr + i*16 + 4);
                ull uk[8];
                uk[0] = pack2(u0.x, u0.x); uk[1] = pack2(u0.y, u0.y);
                uk[2] = pack2(u0.z, u0.z); uk[3] = pack2(u0.w, u0.w);
                uk[4] = pack2(u1.x, u1.x); uk[5] = pack2(u1.y, u1.y);
                uk[6] = pack2(u1.z, u1.z); uk[7] = pack2(u1.w, u1.w);
                #pragma unroll
                for (int j = 0; j < 8; j++) {
                    fma2(acc[j][0], uk[j], mA.x);
                    fma2(acc[j][1], uk[j], mA.y);
                    fma2(acc[j][2], uk[j], mB.x);
                    fma2(acc[j][3], uk[j], mB.y);
                }
            }
            #pragma unroll
            for (int j = 0; j < 8; j++) {
                ulonglong2 vlo; vlo.x = acc[j][0]; vlo.y = acc[j][1];
                ulonglong2 vhi; vhi.x = acc[j][2]; vhi.y = acc[j][3];
                *(ulonglong2*)(Sbase + j*SST)     = vlo;
                *(ulonglong2*)(Sbase + j*SST + 4) = vhi;
            }
        }
        __syncthreads();

        // ---- phase 3: epilogue ----
        {
            float s[4];
            #pragma unroll
            for (int gg = 0; gg < 4; gg++) {
                float v = ubr[gg];
                #pragma unroll
                for (int qq = 0; qq < 16; qq++)
                    v += s_s[((qq*4 + gg)*16 + ek)*SST + eb];
                s[gg] = v;
            }
            s[0] += xp0; s[1] += xp1; s[2] += xp2; s[3] += xp3;
            float iv = __fdividef(1.f, 1.f + __expf(-s[0]));
            float fv = __fdividef(1.f, 1.f + __expf(-s[1]));
            float ov = __fdividef(1.f, 1.f + __expf(-s[2]));
            float gv = __fdividef(2.f, 1.f + __expf(-2.f*s[3])) - 1.f;
            float c  = fv * c_s[tid] + iv * gv;
            c_s[tid] = c;
            float th = __fdividef(2.f, 1.f + __expf(-2.f*c)) - 1.f;
            float hval = ov * th;
            __stcg(&hn[(size_t)t*BH + (b0+eb)*H_SZ + k0+ek], hval);
            if (t == T_STEPS-1) {
                ht_out[(b0+eb)*H_SZ + k0+ek] = hval;
                ct_out[(b0+eb)*H_SZ + k0+ek] = c;
            }
        }

        // ---- phase 4: rendezvous (r11 scheme) + prefetch ----
        if (t < T_STEPS-1) {
            const float* xpn = d_xpre + (((size_t)(t+1)*B_SZ + b0 + eb)*4)*H_SZ + k0 + ek;
            xp0 = __ldcs(xpn);
            xp1 = __ldcs(xpn + H_SZ);
            xp2 = __ldcs(xpn + 2*H_SZ);
            xp3 = __ldcs(xpn + 3*H_SZ);

            __syncthreads();          // all CTA h-stores precede the release
            if (tid == 0) {
                asm volatile("red.release.gpu.add.u32 [%0], %1;"
                             :: "l"(mybar), "r"(1u) : "memory");
                unsigned target = (unsigned)(t+1) * 16u;
                unsigned v;
                do {
                    asm volatile("ld.acquire.gpu.u32 %0, [%1];" : "=r"(v) : "l"(mybar));
                } while (v < target);
            }
            __syncthreads();
        }
    }
}

// ---------------- launcher ----------------
extern "C" void kernel_launch(void* const* d_in, const int* in_sizes, int n_in,
                              void* d_out, int out_size) {
    const float* input = (const float*)d_in[0];
    const float* ux    = (const float*)d_in[1];
    const float* uh    = (const float*)d_in[2];
    const float* W     = (const float*)d_in[3];
    const float* Wb    = (const float*)d_in[4];
    const float* U     = (const float*)d_in[5];
    const float* Ub    = (const float*)d_in[6];
    float* out = (float*)d_out;

    (void)in_sizes; (void)n_in; (void)out_size;

    cudaFuncSetAttribute(recurrent_kernel,
                         cudaFuncAttributeMaxDynamicSharedMemorySize, RK_SMEM_BYTES);

    reset_kernel<<<1, 256>>>();
    mask_kernel<<<512, 256>>>(ux, uh);
    xpre_kernel<<<dim3(T_STEPS, 4, 4), 256>>>(input, W, Wb);
    recurrent_kernel<<<128, RK_THREADS, RK_SMEM_BYTES>>>(U, Ub, out);
}

// round 17
// speedup vs baseline: 1.6230x; 1.6230x over previous
#include <cuda_runtime.h>
#include <cstdint>

#define T_STEPS 512
#define B_SZ 128
#define I_SZ 256
#define H_SZ 256
#define BH (B_SZ*H_SZ)

typedef unsigned long long ull;

// ---------------- f32x2 helpers ----------------
__device__ __forceinline__ ull pack2(float x, float y) {
    ull r; asm("mov.b64 %0, {%1,%2};" : "=l"(r) : "f"(x), "f"(y)); return r;
}
__device__ __forceinline__ void unpack2(float& x, float& y, ull v) {
    asm("mov.b64 {%0,%1}, %2;" : "=f"(x), "=f"(y) : "l"(v));
}
__device__ __forceinline__ void fma2(ull& d, ull a, ull b) {
    asm("fma.rn.f32x2 %0, %1, %2, %0;" : "+l"(d) : "l"(a), "l"(b));
}
__device__ __forceinline__ ull mul2(ull a, ull b) {
    ull r; asm("mul.rn.f32x2 %0, %1, %2;" : "=l"(r) : "l"(a), "l"(b)); return r;
}

// ---------------- device scratch ----------------
__device__ float d_zx[4*B_SZ*I_SZ];                       // (4,B,I)
__device__ float d_zh[4*B_SZ*H_SZ];                       // (4,B,H)
__device__ float d_xpre[(size_t)T_STEPS*B_SZ*4*H_SZ];     // (T,B,4,H)
__device__ unsigned g_bars[8*32];                         // one 128B line per b-group

__global__ void reset_kernel() { if (threadIdx.x < 256) g_bars[threadIdx.x] = 0u; }

// ---------------- masks ----------------
__device__ __forceinline__ float concrete_mask(float u) {
    const float EPSC = 1e-7f;
    float logit_p = logf(0.25f + EPSC) - logf(0.75f + EPSC);
    float lu = logf(u + EPSC) - logf(1.0f - u + EPSC);
    float x = (logit_p + lu) / 0.1f;
    float s = 1.0f / (1.0f + expf(-x));
    return (1.0f - s) / 0.75f;
}

__global__ void mask_kernel(const float* __restrict__ ux, const float* __restrict__ uh) {
    int i = blockIdx.x * blockDim.x + threadIdx.x;
    if (i < 4*B_SZ*I_SZ) {
        d_zx[i] = concrete_mask(ux[i]);
        d_zh[i] = concrete_mask(uh[i]);
    }
}

// ---------------- x_pre GEMM (BK=16, FFMA2) ----------------
#define XB_BM 128
#define XB_BN 64
#define XB_BK 16

__global__ __launch_bounds__(256) void xpre_kernel(
    const float* __restrict__ input, const float* __restrict__ W, const float* __restrict__ Wb)
{
    __shared__ float As[XB_BK][XB_BM+4];
    __shared__ float Bs[XB_BK][XB_BN+4];
    int g  = blockIdx.z;
    int t  = blockIdx.x;
    int n0 = blockIdx.y * XB_BN;
    int tid = threadIdx.x;
    int tx = tid & 15, ty = tid >> 4;

    ull acc[4][4];
    #pragma unroll
    for (int p = 0; p < 4; p++)
        #pragma unroll
        for (int c = 0; c < 4; c++) acc[p][c] = 0ull;

    const float* inpBase = input + (size_t)t * (B_SZ*I_SZ);
    const float* zxBase  = d_zx + g * (B_SZ*I_SZ);
    const float* wBase   = W + (size_t)g * (H_SZ*I_SZ) + (size_t)n0 * I_SZ;

    int lrow   = tid >> 2;
    int lchunk = (tid & 3) * 4;

    for (int kk0 = 0; kk0 < I_SZ; kk0 += XB_BK) {
        #pragma unroll
        for (int it = 0; it < 2; it++) {
            int row = lrow + it*64;
            float4 av = *(const float4*)(inpBase + row*I_SZ + kk0 + lchunk);
            float4 zv = *(const float4*)(zxBase  + row*I_SZ + kk0 + lchunk);
            As[lchunk+0][row] = av.x*zv.x;
            As[lchunk+1][row] = av.y*zv.y;
            As[lchunk+2][row] = av.z*zv.z;
            As[lchunk+3][row] = av.w*zv.w;
        }
        {
            float4 wv = *(const float4*)(wBase + lrow*I_SZ + kk0 + lchunk);
            Bs[lchunk+0][lrow] = wv.x;
            Bs[lchunk+1][lrow] = wv.y;
            Bs[lchunk+2][lrow] = wv.z;
            Bs[lchunk+3][lrow] = wv.w;
        }
        __syncthreads();
        #pragma unroll
        for (int kk = 0; kk < XB_BK; kk++) {
            float4 b4 = *(const float4*)&Bs[kk][tx*4];
            ulonglong2 a01 = *(const ulonglong2*)&As[kk][ty*8];
            ulonglong2 a23 = *(const ulonglong2*)&As[kk][ty*8+4];
            ull ap[4] = {a01.x, a01.y, a23.x, a23.y};
            ull bb[4] = {pack2(b4.x,b4.x), pack2(b4.y,b4.y),
                         pack2(b4.z,b4.z), pack2(b4.w,b4.w)};
            #pragma unroll
            for (int p = 0; p < 4; p++)
                #pragma unroll
                for (int c = 0; c < 4; c++)
                    fma2(acc[p][c], ap[p], bb[c]);
        }
        __syncthreads();
    }
    float4 wb = *(const float4*)(Wb + g*H_SZ + n0 + tx*4);
    #pragma unroll
    for (int p = 0; p < 4; p++) {
        float lo[4], hi[4];
        #pragma unroll
        for (int c = 0; c < 4; c++) unpack2(lo[c], hi[c], acc[p][c]);
        int b0r = ty*8 + 2*p;
        size_t o0 = (((size_t)t*B_SZ + b0r)*4 + g) * H_SZ + n0 + tx*4;
        size_t o1 = (((size_t)t*B_SZ + b0r+1)*4 + g) * H_SZ + n0 + tx*4;
        *(float4*)(d_xpre + o0) = make_float4(lo[0]+wb.x, lo[1]+wb.y, lo[2]+wb.z, lo[3]+wb.w);
        *(float4*)(d_xpre + o1) = make_float4(hi[0]+wb.x, hi[1]+wb.y, hi[2]+wb.z, hi[3]+wb.w);
    }
}

// ---------------- persistent recurrent kernel ----------------
// 128 CTAs (8 b-groups x 16 k-CTAs), 256 threads.
// r11 structure; UQB/HQB padded for conflict-free GEMM reads; pipelined inner loop.
#define RK_THREADS 256
#define UQB 1040                     // 64*16 + 16  (== 16 mod 32: hq halves on disjoint banks)
#define HQB 1168                     // 64*18 + 16  (== 16 mod 32)
#define SST 20                       // 80B row stride (float4-aligned)
#define RK_SMEM_FLOATS (16*UQB + 16*HQB + 4*4*16*SST + 256)
#define RK_SMEM_BYTES (RK_SMEM_FLOATS*4)

__global__ __launch_bounds__(RK_THREADS, 1) void recurrent_kernel(
    const float* __restrict__ U, const float* __restrict__ Ub, float* __restrict__ out)
{
    extern __shared__ float sm[];
    float* U_s  = sm;                        // 16*1040 = 16640
    float* hm_s = U_s + 16*UQB;              // 16*1168 = 18688
    float* s_s  = hm_s + 16*HQB;             // 5120
    float* c_s  = s_s + 4*4*16*SST;          // 256

    int tid = threadIdx.x;
    int bi = blockIdx.x >> 4;  int b0 = bi * 16;
    int ki = blockIdx.x & 15;  int k0 = ki * 16;

    // ---- one-time loads ----
    for (int e = tid; e < 16384; e += RK_THREADS) {       // U_s[(g,hq)][h_in*16+k]
        int g = e >> 12; int k = (e >> 8) & 15; int h = e & 255;
        U_s[(g*4 + (h >> 6))*UQB + (h & 63)*16 + k] =
            U[((size_t)(g*H_SZ + k0 + k))*H_SZ + h];
    }
    for (int e = tid; e < 16*HQB; e += RK_THREADS) hm_s[e] = 0.f;   // t=0 state
    c_s[tid] = 0.f;

    // zh registers: thread h=tid, zr[g][bp] packs batches (2bp, 2bp+1)
    ull zr[4][8];
    {
        int h = tid;
        #pragma unroll
        for (int g = 0; g < 4; g++)
            #pragma unroll
            for (int bp = 0; bp < 8; bp++) {
                float z0 = d_zh[((size_t)(g*B_SZ + b0 + 2*bp))*H_SZ + h];
                float z1 = d_zh[((size_t)(g*B_SZ + b0 + 2*bp+1))*H_SZ + h];
                zr[g][bp] = pack2(z0, z1);
            }
    }

    int eb = tid >> 4, ek = tid & 15;   // epilogue cell (b,k)
    float ubr[4];
    #pragma unroll
    for (int g = 0; g < 4; g++) ubr[g] = Ub[g*H_SZ + k0 + ek];
    __syncthreads();

    // ---- GEMM layout: 8 warps = (hH 0..1) x (g 0..3); lane = (hq2, bq, kq) ----
    int w = tid >> 5, lane = tid & 31;
    int g   = w & 3;
    int hH  = w >> 2;
    int kq  = lane & 3;
    int bq  = (lane >> 2) & 3;
    int hq  = hH*2 + (lane >> 4);
    const float* Ug = U_s  + (g*4 + hq)*UQB + kq*4;
    const float* Hm = hm_s + (g*4 + hq)*HQB + 4*bq;
    float* Sbase = s_s + ((hq*4 + g)*16 + kq*4)*SST + 4*bq;

    float* hn     = out;
    float* ht_out = out + (size_t)T_STEPS*BH;
    float* ct_out = ht_out + BH;

    unsigned* mybar = &g_bars[bi*32];

    // initial x_pre prefetch (t=0)
    const float* xpp = d_xpre + (((size_t)(b0 + eb))*4)*H_SZ + k0 + ek;
    float xp0 = __ldcs(xpp);
    float xp1 = __ldcs(xpp + H_SZ);
    float xp2 = __ldcs(xpp + 2*H_SZ);
    float xp3 = __ldcs(xpp + 3*H_SZ);

    for (int t = 0; t < T_STEPS; t++) {
        // ---- phase 1: stage hm = h_prev * zh (t=0 pre-zeroed) ----
        if (t > 0) {
            const float* hprev = hn + (size_t)(t-1)*BH + (size_t)b0*H_SZ;
            int h = tid;
            int hqi = h >> 6, h_in = h & 63;
            float hv0[8], hv1[8];
            #pragma unroll
            for (int bp = 0; bp < 8; bp++) {
                hv0[bp] = __ldcg(hprev + (2*bp)*H_SZ + h);
                hv1[bp] = __ldcg(hprev + (2*bp+1)*H_SZ + h);
            }
            #pragma unroll
            for (int bp = 0; bp < 8; bp++) {
                ull hp = pack2(hv0[bp], hv1[bp]);
                #pragma unroll
                for (int gg = 0; gg < 4; gg++)
                    *(ull*)&hm_s[(gg*4 + hqi)*HQB + h_in*18 + 2*bp] = mul2(hp, zr[gg][bp]);
            }
        }
        __syncthreads();

        // ---- phase 2: recurrent GEMM, 4k x 4b over 64 h, pipelined ----
        {
            ull a0[2] = {0ull,0ull}, a1[2] = {0ull,0ull};
            ull a2[2] = {0ull,0ull}, a3[2] = {0ull,0ull};
            ulonglong2 u2 = *(const ulonglong2*)(Ug);
            float2 cA = *(const float2*)(Hm);
            float2 cB = *(const float2*)(Hm + 2);
            #pragma unroll 8
            for (int h = 0; h < 64; h++) {
                ulonglong2 nu = u2;
                float2 nA = cA, nB = cB;
                if (h < 63) {
                    nu = *(const ulonglong2*)(Ug + (h+1)*16);
                    nA = *(const float2*)(Hm + (h+1)*18);
                    nB = *(const float2*)(Hm + (h+1)*18 + 2);
                }
                ull m0 = pack2(cA.x, cA.x);
                ull m1 = pack2(cA.y, cA.y);
                ull m2 = pack2(cB.x, cB.x);
                ull m3 = pack2(cB.y, cB.y);
                fma2(a0[0], u2.x, m0); fma2(a0[1], u2.y, m0);
                fma2(a1[0], u2.x, m1); fma2(a1[1], u2.y, m1);
                fma2(a2[0], u2.x, m2); fma2(a2[1], u2.y, m2);
                fma2(a3[0], u2.x, m3); fma2(a3[1], u2.y, m3);
                u2 = nu; cA = nA; cB = nB;
            }
            float f0[4], f1[4], f2[4], f3[4];
            unpack2(f0[0], f0[1], a0[0]); unpack2(f0[2], f0[3], a0[1]);
            unpack2(f1[0], f1[1], a1[0]); unpack2(f1[2], f1[3], a1[1]);
            unpack2(f2[0], f2[1], a2[0]); unpack2(f2[2], f2[3], a2[1]);
            unpack2(f3[0], f3[1], a3[0]); unpack2(f3[2], f3[3], a3[1]);
            #pragma unroll
            for (int kk = 0; kk < 4; kk++)
                *(float4*)(Sbase + kk*SST) = make_float4(f0[kk], f1[kk], f2[kk], f3[kk]);
        }
        __syncthreads();

        // ---- phase 3: epilogue ----
        {
            float s[4];
            #pragma unroll
            for (int gg = 0; gg < 4; gg++) {
                float v = ubr[gg];
                #pragma unroll
                for (int qq = 0; qq < 4; qq++)
                    v += s_s[((qq*4 + gg)*16 + ek)*SST + eb];
                s[gg] = v;
            }
            s[0] += xp0; s[1] += xp1; s[2] += xp2; s[3] += xp3;
            float iv = __fdividef(1.f, 1.f + __expf(-s[0]));
            float fv = __fdividef(1.f, 1.f + __expf(-s[1]));
            float ov = __fdividef(1.f, 1.f + __expf(-s[2]));
            float gv = __fdividef(2.f, 1.f + __expf(-2.f*s[3])) - 1.f;
            float c  = fv * c_s[tid] + iv * gv;
            c_s[tid] = c;
            float th = __fdividef(2.f, 1.f + __expf(-2.f*c)) - 1.f;
            float hval = ov * th;
            __stcg(&hn[(size_t)t*BH + (b0+eb)*H_SZ + k0+ek], hval);
            if (t == T_STEPS-1) {
                ht_out[(b0+eb)*H_SZ + k0+ek] = hval;
                ct_out[(b0+eb)*H_SZ + k0+ek] = c;
            }
        }

        // ---- phase 4: rendezvous + next-step x_pre prefetch ----
        if (t < T_STEPS-1) {
            const float* xpn = d_xpre + (((size_t)(t+1)*B_SZ + b0 + eb)*4)*H_SZ + k0 + ek;
            xp0 = __ldcs(xpn);
            xp1 = __ldcs(xpn + H_SZ);
            xp2 = __ldcs(xpn + 2*H_SZ);
            xp3 = __ldcs(xpn + 3*H_SZ);

            __syncthreads();          // all CTA h-stores precede the release
            if (tid == 0) {
                asm volatile("red.release.gpu.add.u32 [%0], %1;"
                             :: "l"(mybar), "r"(1u) : "memory");
                unsigned target = (unsigned)(t+1) * 16u;
                unsigned v;
                do {
                    asm volatile("ld.acquire.gpu.u32 %0, [%1];" : "=r"(v) : "l"(mybar));
                } while (v < target);
            }
            __syncthreads();
        }
    }
}

// ---------------- launcher ----------------
extern "C" void kernel_launch(void* const* d_in, const int* in_sizes, int n_in,
                              void* d_out, int out_size) {
    const float* input = (const float*)d_in[0];
    const float* ux    = (const float*)d_in[1];
    const float* uh    = (const float*)d_in[2];
    const float* W     = (const float*)d_in[3];
    const float* Wb    = (const float*)d_in[4];
    const float* U     = (const float*)d_in[5];
    const float* Ub    = (const float*)d_in[6];
    float* out = (float*)d_out;

    (void)in_sizes; (void)n_in; (void)out_size;

    cudaFuncSetAttribute(recurrent_kernel,
                         cudaFuncAttributeMaxDynamicSharedMemorySize, RK_SMEM_BYTES);

    reset_kernel<<<1, 256>>>();
    mask_kernel<<<512, 256>>>(ux, uh);
    xpre_kernel<<<dim3(T_STEPS, 4, 4), 256>>>(input, W, Wb);
    recurrent_kernel<<<128, RK_THREADS, RK_SMEM_BYTES>>>(U, Ub, out);
}